// round 7
// baseline (speedup 1.0000x reference)
#include <cuda_runtime.h>
#include <math.h>
#include <stdint.h>

#define C_IN   384
#define C_MID  1536
#define EMB_D  1024
#define BATCH  16
#define HW     1024
#define GROUPS 32
#define CPG    12
#define EPSV   1e-5f

#define BM 128
#define BN 128
#define BK 32
#define LDB 136
#define A_STG 4096
#define B_STG (BK * LDB)
#define STG_F (A_STG + B_STG)
#define NSTAGE 3
#define SMEMB (NSTAGE * STG_F * 4 + 1024)

// Column permutation within each 32-col block: p = (c&7)*4 + (c>>3).
// Activations (g_xn, g_h) are stored permuted; weights output of GEMM2 is standard.

// ---------------- device scratch ----------------
__device__ float g_h[(size_t)BATCH * C_MID * HW];     // h, tf32-rounded, col-permuted
__device__ float g_xn[(size_t)BATCH * C_IN * HW];     // xn, tf32-rounded, col-permuted
__device__ float g_embout[BATCH * 2 * C_MID];
__device__ float g_w1f[C_MID * C_IN];                 // w1 fragment-order, tf32
__device__ float g_w2f[C_IN * C_MID];                 // w2 fragment-order, tf32

// ---------------- helpers ----------------
__device__ __forceinline__ float tf32r(float f) {
    uint32_t u; asm("cvt.rna.tf32.f32 %0, %1;" : "=r"(u) : "f"(f));
    return __uint_as_float(u);
}
__device__ __forceinline__ void mma8(float* c, const uint32_t* a, const uint32_t* b) {
    asm volatile(
        "mma.sync.aligned.m16n8k8.row.col.f32.tf32.tf32.f32 "
        "{%0,%1,%2,%3}, {%4,%5,%6,%7}, {%8,%9}, {%0,%1,%2,%3};\n"
        : "+f"(c[0]), "+f"(c[1]), "+f"(c[2]), "+f"(c[3])
        : "r"(a[0]), "r"(a[1]), "r"(a[2]), "r"(a[3]), "r"(b[0]), "r"(b[1]));
}
__device__ __forceinline__ void cp16(float* s, const float* g) {
    uint32_t sa = (uint32_t)__cvta_generic_to_shared(s);
    asm volatile("cp.async.cg.shared.global [%0], [%1], 16;\n" :: "r"(sa), "l"(g));
}
#define CPCOMMIT() asm volatile("cp.async.commit_group;\n" ::: "memory")
#define CPWAIT(n)  asm volatile("cp.async.wait_group %0;\n" :: "n"(n) : "memory")

// ---------------------------------------------------------------------------
// Weight -> fragment-order (+ tf32 rounding). [mb,s][kk(4)][mt(8)][lane(32)][q(4)]
// ---------------------------------------------------------------------------
__global__ void __launch_bounds__(256) wtrans(const float* __restrict__ w,
                                              float* __restrict__ wf,
                                              int M, int K) {
    int i = blockIdx.x * 256 + threadIdx.x;
    if (i >= M * K) return;
    int m = i / K, k = i % K;
    int S = K >> 5;
    int mb = m >> 7, s = k >> 5, kk = (k >> 3) & 3, mt = (m >> 4) & 7;
    int r = m & 15, c = k & 7;
    int q = (r >> 3) | ((c >> 2) << 1);
    int lane = (r & 7) * 4 + (c & 3);
    size_t dst = ((((size_t)(mb * S + s) * 4 + kk) * 8 + mt) * 32 + lane) * 4 + q;
    wf[dst] = tf32r(w[i]);
}

// ---------------------------------------------------------------------------
__global__ void __launch_bounds__(256) emb_gemm(const float* __restrict__ emb,
                                                const float* __restrict__ we,
                                                const float* __restrict__ be) {
    int w = threadIdx.x >> 5, lane = threadIdx.x & 31;
    int j = blockIdx.x * 8 + w;
    const float4* wrow = (const float4*)(we + (size_t)j * EMB_D);
    float4 wv[8];
#pragma unroll
    for (int i = 0; i < 8; i++) wv[i] = wrow[lane + 32 * i];
#pragma unroll
    for (int b = 0; b < BATCH; b++) {
        const float4* er = (const float4*)(emb + (size_t)b * EMB_D);
        float acc = 0.f;
#pragma unroll
        for (int i = 0; i < 8; i++) {
            float4 ev = __ldg(&er[lane + 32 * i]);
            acc += wv[i].x * ev.x + wv[i].y * ev.y + wv[i].z * ev.z + wv[i].w * ev.w;
        }
#pragma unroll
        for (int off = 16; off; off >>= 1) acc += __shfl_xor_sync(0xffffffffu, acc, off);
        if (lane == 0) g_embout[b * (2 * C_MID) + j] = acc + be[j];
    }
}

// ---------------------------------------------------------------------------
// GroupNorm stats + fused xn write (tf32-rounded, column-permuted).
// ---------------------------------------------------------------------------
__global__ void __launch_bounds__(256) gn_xn(const float* __restrict__ x,
                                             const float* __restrict__ gn_w,
                                             const float* __restrict__ gn_b) {
    int g = blockIdx.x, b = blockIdx.y;
    const size_t rowbase = ((size_t)b * C_IN + (size_t)g * CPG) * HW;
    const float* xp = x + rowbase;
    int t = threadIdx.x;
    const int N = CPG * HW;

    float s = 0.f, ss = 0.f;
    for (int i = t * 4; i < N; i += 256 * 4) {
        float4 v = *(const float4*)(xp + i);
        s  += v.x + v.y + v.z + v.w;
        ss += v.x * v.x + v.y * v.y + v.z * v.z + v.w * v.w;
    }
#pragma unroll
    for (int off = 16; off; off >>= 1) {
        s  += __shfl_xor_sync(0xffffffffu, s, off);
        ss += __shfl_xor_sync(0xffffffffu, ss, off);
    }
    __shared__ float rs[8], rss[8];
    if ((t & 31) == 0) { rs[t >> 5] = s; rss[t >> 5] = ss; }
    __syncthreads();
    __shared__ float smu, srst;
    if (t == 0) {
        float S = 0.f, SS = 0.f;
#pragma unroll
        for (int i = 0; i < 8; i++) { S += rs[i]; SS += rss[i]; }
        float mu  = S / (float)N;
        float var = SS / (float)N - mu * mu;
        smu = mu; srst = rsqrtf(var + EPSV);
    }
    __syncthreads();
    const float mu = smu, rst = srst;

    // fused xn: thread t handles (nb = t>>3, v = t&7) for each of 12 channels.
    // store float4 at permuted position nb*32 + v*4, sources cols v, v+8, v+16, v+24.
    const int nb = t >> 3, v = t & 7;
#pragma unroll
    for (int ch = 0; ch < CPG; ch++) {
        int c = g * CPG + ch;
        float a  = rst * gn_w[c];
        float bb = gn_b[c] - mu * a;
        const float* xr = x + ((size_t)b * C_IN + c) * HW + nb * 32;
        float4 o;
        o.x = tf32r(xr[v]      * a + bb);
        o.y = tf32r(xr[v + 8]  * a + bb);
        o.z = tf32r(xr[v + 16] * a + bb);
        o.w = tf32r(xr[v + 24] * a + bb);
        *(float4*)(g_xn + ((size_t)b * C_IN + c) * HW + nb * 32 + v * 4) = o;
    }
}

// ---------------------------------------------------------------------------
// tf32 mma.sync GEMM. A: fragment-order weights (LDS.128). B: permuted
// activations (LDS.128 frags). 128x128x32, 3-stage cp.async ring, 8 warps.
// EPI==1: -> g_h (tf32, permuted cols). EPI==2: out = x + acc + b2 (standard).
// ---------------------------------------------------------------------------
template <int KTOT, int MTOT, int EPI>
__global__ void __launch_bounds__(256, 2) mma_gemm(
    const float* __restrict__ Wf,
    const float* __restrict__ Bsrc,
    const float* __restrict__ bias,
    const float* __restrict__ xres,
    float* __restrict__ outp)
{
    extern __shared__ float dsm[];
    float* sm = (float*)(((uintptr_t)dsm + 1023) & ~(uintptr_t)1023);

    const int t = threadIdx.x;
    const int b = blockIdx.z;
    const int m0 = blockIdx.x * BM;
    const int p0 = blockIdx.y * BN;
    const int wid = t >> 5, lane = t & 31;
    const int gr = lane >> 2, tg = lane & 3;
    const int mt4 = (wid >> 2) * 4;
    const int nw = (wid & 3) * 32;
    const int S = KTOT / BK;

    const float* Wb = Wf + (size_t)blockIdx.x * S * A_STG;
    const float* Bb = Bsrc + (size_t)b * KTOT * HW + p0;

    float acc[4][4][4];
#pragma unroll
    for (int i = 0; i < 4; i++)
#pragma unroll
        for (int j = 0; j < 4; j++)
#pragma unroll
            for (int q = 0; q < 4; q++) acc[i][j][q] = 0.f;

    auto fill = [&](int st) {
        float* sA = sm + (st % NSTAGE) * STG_F;
        float* sB = sA + A_STG;
        const float* gA = Wb + (size_t)st * A_STG;
#pragma unroll
        for (int it = 0; it < 4; it++)
            cp16(sA + t * 4 + it * 1024, gA + t * 4 + it * 1024);
        const int k0 = st * BK;
#pragma unroll
        for (int it = 0; it < 4; it++) {
            int idx = t + it * 256;
            int k = idx >> 5, c4 = idx & 31;
            cp16(sB + k * LDB + c4 * 4, Bb + (size_t)(k0 + k) * HW + c4 * 4);
        }
        CPCOMMIT();
    };

    fill(0);
    if (S > 1) fill(1);

    for (int s = 0; s < S; s++) {
        if (s + 1 < S) CPWAIT(1); else CPWAIT(0);
        __syncthreads();
        if (s + 2 < S) fill(s + 2);

        const float* sA = sm + (s % NSTAGE) * STG_F;
        const float* sB = sA + A_STG;

#pragma unroll
        for (int kk = 0; kk < 4; kk++) {
            uint32_t af[4][4];
#pragma unroll
            for (int mi = 0; mi < 4; mi++) {
                const float4 v = *(const float4*)(sA + ((kk * 8 + mt4 + mi) * 32 + lane) * 4);
                af[mi][0] = __float_as_uint(v.x);
                af[mi][1] = __float_as_uint(v.y);
                af[mi][2] = __float_as_uint(v.z);
                af[mi][3] = __float_as_uint(v.w);
            }
            // B frags: permuted layout -> one LDS.128 per row, rows tg and tg+4
            const float4 u0 = *(const float4*)(sB + (kk * 8 + tg)     * LDB + nw + gr * 4);
            const float4 u1 = *(const float4*)(sB + (kk * 8 + tg + 4) * LDB + nw + gr * 4);
            uint32_t bf[4][2];
            bf[0][0] = __float_as_uint(u0.x); bf[0][1] = __float_as_uint(u1.x);
            bf[1][0] = __float_as_uint(u0.y); bf[1][1] = __float_as_uint(u1.y);
            bf[2][0] = __float_as_uint(u0.z); bf[2][1] = __float_as_uint(u1.z);
            bf[3][0] = __float_as_uint(u0.w); bf[3][1] = __float_as_uint(u1.w);
#pragma unroll
            for (int mi = 0; mi < 4; mi++)
#pragma unroll
                for (int ni = 0; ni < 4; ni++)
                    mma8(acc[mi][ni], af[mi], bf[ni]);
        }
    }

    // ---------------- epilogue ----------------
    const int mw = mt4 * 16;
    if (EPI == 1) {
        const float* sc = g_embout + b * 2 * C_MID;
#pragma unroll
        for (int mi = 0; mi < 4; mi++) {
#pragma unroll
            for (int half = 0; half < 2; half++) {
                int r = m0 + mw + mi * 16 + gr + half * 8;
                float bi    = bias[r];
                float scale = 1.f + sc[r];
                float shift = sc[C_MID + r];
                float* orow = g_h + ((size_t)b * C_MID + r) * HW + p0 + nw + tg * 8;
                float e0[4], e1[4];
#pragma unroll
                for (int ni = 0; ni < 4; ni++) {
                    float v0 = acc[mi][ni][half * 2]     + bi;
                    float v1 = acc[mi][ni][half * 2 + 1] + bi;
                    v0 = v0 / (1.f + __expf(-v0));
                    v1 = v1 / (1.f + __expf(-v1));
                    e0[ni] = tf32r(v0 * scale + shift);
                    e1[ni] = tf32r(v1 * scale + shift);
                }
                // permuted: cols (ni*8 + tg*2 + e) -> positions tg*8 + 4e + ni
                *(float4*)(orow)     = make_float4(e0[0], e0[1], e0[2], e0[3]);
                *(float4*)(orow + 4) = make_float4(e1[0], e1[1], e1[2], e1[3]);
            }
        }
    } else {
#pragma unroll
        for (int mi = 0; mi < 4; mi++) {
#pragma unroll
            for (int half = 0; half < 2; half++) {
                int r = m0 + mw + mi * 16 + gr + half * 8;
                float bi = bias[r];
                const float* xrow = xres + ((size_t)b * C_IN + r) * HW + p0 + nw;
                float* orow = outp + ((size_t)b * C_IN + r) * HW + p0 + nw;
#pragma unroll
                for (int ni = 0; ni < 4; ni++) {
                    float2 xv = *(const float2*)(xrow + ni * 8 + tg * 2);
                    float2 o = make_float2(xv.x + acc[mi][ni][half * 2]     + bi,
                                           xv.y + acc[mi][ni][half * 2 + 1] + bi);
                    *(float2*)(orow + ni * 8 + tg * 2) = o;
                }
            }
        }
    }
}

// ---------------------------------------------------------------------------
extern "C" void kernel_launch(void* const* d_in, const int* in_sizes, int n_in,
                              void* d_out, int out_size) {
    const float* x    = (const float*)d_in[0];
    const float* emb  = (const float*)d_in[1];
    const float* gn_w = (const float*)d_in[2];
    const float* gn_b = (const float*)d_in[3];
    const float* w1   = (const float*)d_in[4];
    const float* b1   = (const float*)d_in[5];
    const float* we   = (const float*)d_in[6];
    const float* be   = (const float*)d_in[7];
    const float* w2   = (const float*)d_in[8];
    const float* b2   = (const float*)d_in[9];
    float* out = (float*)d_out;

    float *hbuf, *xnbuf, *w1f, *w2f;
    cudaGetSymbolAddress((void**)&hbuf, g_h);
    cudaGetSymbolAddress((void**)&xnbuf, g_xn);
    cudaGetSymbolAddress((void**)&w1f, g_w1f);
    cudaGetSymbolAddress((void**)&w2f, g_w2f);

    cudaFuncSetAttribute(mma_gemm<C_IN, C_MID, 1>,
                         cudaFuncAttributeMaxDynamicSharedMemorySize, SMEMB);
    cudaFuncSetAttribute(mma_gemm<C_MID, C_IN, 2>,
                         cudaFuncAttributeMaxDynamicSharedMemorySize, SMEMB);

    wtrans<<<(C_MID * C_IN + 255) / 256, 256>>>(w1, w1f, C_MID, C_IN);
    wtrans<<<(C_IN * C_MID + 255) / 256, 256>>>(w2, w2f, C_IN, C_MID);
    emb_gemm<<<(2 * C_MID) / 8, 256>>>(emb, we, be);
    gn_xn<<<dim3(GROUPS, BATCH), 256>>>(x, gn_w, gn_b);

    mma_gemm<C_IN, C_MID, 1><<<dim3(C_MID / BM, HW / BN, BATCH), 256, SMEMB>>>(
        w1f, xnbuf, b1, nullptr, nullptr);
    mma_gemm<C_MID, C_IN, 2><<<dim3(C_IN / BM, HW / BN, BATCH), 256, SMEMB>>>(
        w2f, hbuf, b2, x, out);
}

// round 8
// speedup vs baseline: 1.6141x; 1.6141x over previous
#include <cuda_runtime.h>
#include <cuda_fp16.h>
#include <math.h>
#include <stdint.h>

#define C_IN   384
#define C_MID  1536
#define EMB_D  1024
#define BATCH  16
#define HW     1024
#define GROUPS 32
#define CPG    12
#define EPSV   1e-5f

#define BM 128
#define BN 128
#define BK 32
#define LDBH 136                         // B smem pitch in u32 (128 data + 8 pad)
#define A_U32 2048                       // A stage: 128x32 fp16 = 2048 u32
#define B_U32 (16 * LDBH)                // B stage: 16 pair-rows
#define STG_U32 (A_U32 + B_U32)
#define NSTAGE 4
#define SMEMB (NSTAGE * STG_U32 * 4 + 1024)
#define LDT 132

typedef unsigned int u32;

// ---------------- device scratch ----------------
__device__ u32 g_h[(size_t)BATCH * (C_MID / 2) * HW];   // h fp16 pair-major (50MB)
__device__ u32 g_xn[(size_t)BATCH * (C_IN / 2) * HW];   // xn fp16 pair-major
__device__ float g_embout[BATCH * 2 * C_MID];
__device__ __half g_w1f[C_MID * C_IN];                  // w1 fragment-order fp16
__device__ __half g_w2f[C_IN * C_MID];                  // w2 fragment-order fp16

// ---------------- helpers ----------------
__device__ __forceinline__ u32 packh(float lo, float hi) {
    __half2 h = __floats2half2_rn(lo, hi);
    return *(u32*)&h;
}
__device__ __forceinline__ void mma16(float* c, const u32* a, const u32* b) {
    asm volatile(
        "mma.sync.aligned.m16n8k16.row.col.f32.f16.f16.f32 "
        "{%0,%1,%2,%3}, {%4,%5,%6,%7}, {%8,%9}, {%0,%1,%2,%3};\n"
        : "+f"(c[0]), "+f"(c[1]), "+f"(c[2]), "+f"(c[3])
        : "r"(a[0]), "r"(a[1]), "r"(a[2]), "r"(a[3]), "r"(b[0]), "r"(b[1]));
}
__device__ __forceinline__ void cp16(const void* s, const void* g) {
    uint32_t sa = (uint32_t)__cvta_generic_to_shared(s);
    asm volatile("cp.async.cg.shared.global [%0], [%1], 16;\n" :: "r"(sa), "l"(g));
}
#define CPCOMMIT() asm volatile("cp.async.commit_group;\n" ::: "memory")
#define CPWAIT(n)  asm volatile("cp.async.wait_group %0;\n" :: "n"(n) : "memory")

// ---------------------------------------------------------------------------
// Weight -> m16n8k16 fragment order fp16.
// Per (mb, stage s): 2048 u32 = [kk(2)][mt(8)][lane(32)][q(4)], halves within u32.
// ---------------------------------------------------------------------------
__global__ void __launch_bounds__(256) wtrans(const float* __restrict__ w,
                                              __half* __restrict__ wf,
                                              int M, int K) {
    int i = blockIdx.x * 256 + threadIdx.x;
    if (i >= M * K) return;
    int m = i / K, k = i % K;
    int S = K >> 5;
    int mb = m >> 7, s = k >> 5;
    int kk = (k >> 4) & 1;
    int mt = (m >> 4) & 7;
    int r = m & 15, c = k & 15;
    int q = (r >> 3) | ((c >> 3) << 1);
    int lane = (r & 7) * 4 + ((c & 7) >> 1);
    size_t b32i = ((((size_t)(mb * S + s) * 2 + kk) * 8 + mt) * 32 + lane) * 4 + q;
    wf[b32i * 2 + (c & 1)] = __float2half_rn(w[i]);
}

// ---------------------------------------------------------------------------
__global__ void __launch_bounds__(256) emb_gemm(const float* __restrict__ emb,
                                                const float* __restrict__ we,
                                                const float* __restrict__ be) {
    int w = threadIdx.x >> 5, lane = threadIdx.x & 31;
    int j = blockIdx.x * 8 + w;
    const float4* wrow = (const float4*)(we + (size_t)j * EMB_D);
    float4 wv[8];
#pragma unroll
    for (int i = 0; i < 8; i++) wv[i] = wrow[lane + 32 * i];
#pragma unroll
    for (int b = 0; b < BATCH; b++) {
        const float4* er = (const float4*)(emb + (size_t)b * EMB_D);
        float acc = 0.f;
#pragma unroll
        for (int i = 0; i < 8; i++) {
            float4 ev = __ldg(&er[lane + 32 * i]);
            acc += wv[i].x * ev.x + wv[i].y * ev.y + wv[i].z * ev.z + wv[i].w * ev.w;
        }
#pragma unroll
        for (int off = 16; off; off >>= 1) acc += __shfl_xor_sync(0xffffffffu, acc, off);
        if (lane == 0) g_embout[b * (2 * C_MID) + j] = acc + be[j];
    }
}

// ---------------------------------------------------------------------------
// GroupNorm stats + fused xn write (fp16, k-pair-major).
// ---------------------------------------------------------------------------
__global__ void __launch_bounds__(256) gn_xn(const float* __restrict__ x,
                                             const float* __restrict__ gn_w,
                                             const float* __restrict__ gn_b) {
    int g = blockIdx.x, b = blockIdx.y;
    const float* xp = x + ((size_t)b * C_IN + (size_t)g * CPG) * HW;
    int t = threadIdx.x;
    const int N = CPG * HW;

    float s = 0.f, ss = 0.f;
    for (int i = t * 4; i < N; i += 256 * 4) {
        float4 v = *(const float4*)(xp + i);
        s  += v.x + v.y + v.z + v.w;
        ss += v.x * v.x + v.y * v.y + v.z * v.z + v.w * v.w;
    }
#pragma unroll
    for (int off = 16; off; off >>= 1) {
        s  += __shfl_xor_sync(0xffffffffu, s, off);
        ss += __shfl_xor_sync(0xffffffffu, ss, off);
    }
    __shared__ float rs[8], rss[8];
    if ((t & 31) == 0) { rs[t >> 5] = s; rss[t >> 5] = ss; }
    __syncthreads();
    __shared__ float smu, srst;
    if (t == 0) {
        float S = 0.f, SS = 0.f;
#pragma unroll
        for (int i = 0; i < 8; i++) { S += rs[i]; SS += rss[i]; }
        float mu  = S / (float)N;
        float var = SS / (float)N - mu * mu;
        smu = mu; srst = rsqrtf(var + EPSV);
    }
    __syncthreads();
    const float mu = smu, rst = srst;

    const int n4 = t * 4;
#pragma unroll
    for (int j = 0; j < CPG / 2; j++) {
        int c0 = g * CPG + j * 2;
        float a0 = rst * gn_w[c0],     b0 = gn_b[c0]     - mu * a0;
        float a1 = rst * gn_w[c0 + 1], b1 = gn_b[c0 + 1] - mu * a1;
        float4 x0 = *(const float4*)(x + ((size_t)b * C_IN + c0)     * HW + n4);
        float4 x1 = *(const float4*)(x + ((size_t)b * C_IN + c0 + 1) * HW + n4);
        uint4 o;
        o.x = packh(x0.x * a0 + b0, x1.x * a1 + b1);
        o.y = packh(x0.y * a0 + b0, x1.y * a1 + b1);
        o.z = packh(x0.z * a0 + b0, x1.z * a1 + b1);
        o.w = packh(x0.w * a0 + b0, x1.w * a1 + b1);
        *(uint4*)(g_xn + ((size_t)b * (C_IN / 2) + (c0 >> 1)) * HW + n4) = o;
    }
}

// ---------------------------------------------------------------------------
// fp16 m16n8k16 mma.sync GEMM. 128x128x32, 4-stage cp.async ring, 8 warps.
// A: fragment-order fp16 weights (LDS.128). B: pair-major fp16 acts (LDS.32).
// EPI==1: silu+FiLM -> g_h (fp16 pair-major, via smem repack).
// EPI==2: out = x + acc + b2 (fp32).
// ---------------------------------------------------------------------------
template <int KTOT, int MTOT, int EPI>
__global__ void __launch_bounds__(256, 2) mma_gemm(
    const __half* __restrict__ Wf,
    const u32* __restrict__ Bsrc,
    const float* __restrict__ bias,
    const float* __restrict__ xres,
    float* __restrict__ outp)
{
    extern __shared__ float dsm[];
    u32* sm = (u32*)(((uintptr_t)dsm + 1023) & ~(uintptr_t)1023);

    const int t = threadIdx.x;
    const int b = blockIdx.z;
    const int m0 = blockIdx.x * BM;
    const int p0 = blockIdx.y * BN;
    const int wid = t >> 5, lane = t & 31;
    const int gr = lane >> 2, tg = lane & 3;
    const int mt4 = (wid >> 2) * 4;
    const int nw = (wid & 3) * 32;
    const int S = KTOT / BK;

    const u32* Wb = (const u32*)Wf + (size_t)blockIdx.x * S * A_U32;
    const u32* Bb = Bsrc + (size_t)b * (KTOT / 2) * HW + p0;

    float acc[4][4][4];
#pragma unroll
    for (int i = 0; i < 4; i++)
#pragma unroll
        for (int j = 0; j < 4; j++)
#pragma unroll
            for (int q = 0; q < 4; q++) acc[i][j][q] = 0.f;

    auto fill = [&](int st) {
        u32* sA = sm + (st % NSTAGE) * STG_U32;
        u32* sB = sA + A_U32;
        const u32* gA = Wb + (size_t)st * A_U32;
        cp16(sA + t * 4,        gA + t * 4);
        cp16(sA + 1024 + t * 4, gA + 1024 + t * 4);
#pragma unroll
        for (int it = 0; it < 2; it++) {
            int idx = t + it * 256;            // 0..511
            int row = idx >> 5, c4 = (idx & 31) * 4;
            cp16(sB + row * LDBH + c4, Bb + (size_t)(st * 16 + row) * HW + c4);
        }
        CPCOMMIT();
    };

    fill(0); fill(1); fill(2);

    for (int s = 0; s < S; s++) {
        if (s + 3 < S) { CPWAIT(2); }
        else if (s + 2 < S) { CPWAIT(2); }
        else if (s + 1 < S) { CPWAIT(1); }
        else { CPWAIT(0); }
        __syncthreads();
        if (s + 3 < S) fill(s + 3);

        const u32* sA = sm + (s % NSTAGE) * STG_U32;
        const u32* sB = sA + A_U32;

#pragma unroll
        for (int kk = 0; kk < 2; kk++) {
            u32 af[4][4];
#pragma unroll
            for (int mi = 0; mi < 4; mi++) {
                const uint4 v = *(const uint4*)(sA + ((kk * 8 + mt4 + mi) * 32 + lane) * 4);
                af[mi][0] = v.x; af[mi][1] = v.y; af[mi][2] = v.z; af[mi][3] = v.w;
            }
            u32 bf[4][2];
#pragma unroll
            for (int ni = 0; ni < 4; ni++) {
                int nc = nw + ni * 8 + gr;
                bf[ni][0] = sB[(kk * 8 + tg)     * LDBH + nc];
                bf[ni][1] = sB[(kk * 8 + tg + 4) * LDBH + nc];
            }
#pragma unroll
            for (int mi = 0; mi < 4; mi++)
#pragma unroll
                for (int ni = 0; ni < 4; ni++)
                    mma16(acc[mi][ni], af[mi], bf[ni]);
        }
        __syncthreads();
    }

    // ---------------- epilogue ----------------
    const int mw = mt4 * 16;
    if (EPI == 1) {
        // stage fp32 results in smem, then repack to fp16 pair-major, coalesced.
        float* tile = (float*)sm;
        const float* sc = g_embout + b * 2 * C_MID;
#pragma unroll
        for (int mi = 0; mi < 4; mi++) {
#pragma unroll
            for (int half = 0; half < 2; half++) {
                int rl = mw + mi * 16 + gr + half * 8;
                int r = m0 + rl;
                float bi    = bias[r];
                float scale = 1.f + sc[r];
                float shift = sc[C_MID + r];
#pragma unroll
                for (int ni = 0; ni < 4; ni++) {
                    float v0 = acc[mi][ni][half * 2]     + bi;
                    float v1 = acc[mi][ni][half * 2 + 1] + bi;
                    v0 = v0 / (1.f + __expf(-v0));
                    v1 = v1 / (1.f + __expf(-v1));
                    float2 o = make_float2(v0 * scale + shift, v1 * scale + shift);
                    *(float2*)(tile + rl * LDT + nw + ni * 8 + tg * 2) = o;
                }
            }
        }
        __syncthreads();
#pragma unroll
        for (int it = 0; it < 8; it++) {
            int idx = t + it * 256;            // 0..2047
            int p = idx >> 5, c4 = (idx & 31) * 4;
            const float* r0 = tile + (2 * p)     * LDT + c4;
            const float* r1 = tile + (2 * p + 1) * LDT + c4;
            uint4 o;
            o.x = packh(r0[0], r1[0]);
            o.y = packh(r0[1], r1[1]);
            o.z = packh(r0[2], r1[2]);
            o.w = packh(r0[3], r1[3]);
            *(uint4*)(g_h + ((size_t)b * (C_MID / 2) + (m0 >> 1) + p) * HW + p0 + c4) = o;
        }
    } else {
#pragma unroll
        for (int mi = 0; mi < 4; mi++) {
#pragma unroll
            for (int half = 0; half < 2; half++) {
                int r = m0 + mw + mi * 16 + gr + half * 8;
                float bi = bias[r];
                const float* xrow = xres + ((size_t)b * C_IN + r) * HW + p0 + nw;
                float* orow = outp + ((size_t)b * C_IN + r) * HW + p0 + nw;
#pragma unroll
                for (int ni = 0; ni < 4; ni++) {
                    float2 xv = *(const float2*)(xrow + ni * 8 + tg * 2);
                    float2 o = make_float2(xv.x + acc[mi][ni][half * 2]     + bi,
                                           xv.y + acc[mi][ni][half * 2 + 1] + bi);
                    *(float2*)(orow + ni * 8 + tg * 2) = o;
                }
            }
        }
    }
}

// ---------------------------------------------------------------------------
extern "C" void kernel_launch(void* const* d_in, const int* in_sizes, int n_in,
                              void* d_out, int out_size) {
    const float* x    = (const float*)d_in[0];
    const float* emb  = (const float*)d_in[1];
    const float* gn_w = (const float*)d_in[2];
    const float* gn_b = (const float*)d_in[3];
    const float* w1   = (const float*)d_in[4];
    const float* b1   = (const float*)d_in[5];
    const float* we   = (const float*)d_in[6];
    const float* be   = (const float*)d_in[7];
    const float* w2   = (const float*)d_in[8];
    const float* b2   = (const float*)d_in[9];
    float* out = (float*)d_out;

    u32 *hbuf, *xnbuf;
    __half *w1f, *w2f;
    cudaGetSymbolAddress((void**)&hbuf, g_h);
    cudaGetSymbolAddress((void**)&xnbuf, g_xn);
    cudaGetSymbolAddress((void**)&w1f, g_w1f);
    cudaGetSymbolAddress((void**)&w2f, g_w2f);

    cudaFuncSetAttribute(mma_gemm<C_IN, C_MID, 1>,
                         cudaFuncAttributeMaxDynamicSharedMemorySize, SMEMB);
    cudaFuncSetAttribute(mma_gemm<C_MID, C_IN, 2>,
                         cudaFuncAttributeMaxDynamicSharedMemorySize, SMEMB);

    wtrans<<<(C_MID * C_IN + 255) / 256, 256>>>(w1, w1f, C_MID, C_IN);
    wtrans<<<(C_IN * C_MID + 255) / 256, 256>>>(w2, w2f, C_IN, C_MID);
    emb_gemm<<<(2 * C_MID) / 8, 256>>>(emb, we, be);
    gn_xn<<<dim3(GROUPS, BATCH), 256>>>(x, gn_w, gn_b);

    mma_gemm<C_IN, C_MID, 1><<<dim3(C_MID / BM, HW / BN, BATCH), 256, SMEMB>>>(
        w1f, xnbuf, b1, nullptr, nullptr);
    mma_gemm<C_MID, C_IN, 2><<<dim3(C_IN / BM, HW / BN, BATCH), 256, SMEMB>>>(
        w2f, hbuf, b2, x, out);
}

// round 10
// speedup vs baseline: 1.6563x; 1.0262x over previous
#include <cuda_runtime.h>
#include <cuda_fp16.h>
#include <math.h>
#include <stdint.h>

#define C_IN   384
#define C_MID  1536
#define EMB_D  1024
#define BATCH  16
#define HW     1024
#define GROUPS 32
#define CPG    12
#define EPSV   1e-5f

#define BM 128
#define BN 128
#define LDBH 136
#define LDT 132

typedef unsigned int u32;

// ---------------- device scratch ----------------
__device__ u32 g_h[(size_t)BATCH * (C_MID / 2) * HW];   // h fp16 pair-major
__device__ u32 g_xn[(size_t)BATCH * (C_IN / 2) * HW];   // xn fp16 pair-major
__device__ float g_embout[BATCH * 2 * C_MID];
__device__ __half g_w1f[C_MID * C_IN];
__device__ __half g_w2f[C_IN * C_MID];

// ---------------- helpers ----------------
__device__ __forceinline__ u32 packh(float lo, float hi) {
    __half2 h = __floats2half2_rn(lo, hi);
    return *(u32*)&h;
}
__device__ __forceinline__ void mma16(float* c, const u32* a, const u32* b) {
    asm volatile(
        "mma.sync.aligned.m16n8k16.row.col.f32.f16.f16.f32 "
        "{%0,%1,%2,%3}, {%4,%5,%6,%7}, {%8,%9}, {%0,%1,%2,%3};\n"
        : "+f"(c[0]), "+f"(c[1]), "+f"(c[2]), "+f"(c[3])
        : "r"(a[0]), "r"(a[1]), "r"(a[2]), "r"(a[3]), "r"(b[0]), "r"(b[1]));
}
__device__ __forceinline__ void cp16(const void* s, const void* g) {
    uint32_t sa = (uint32_t)__cvta_generic_to_shared(s);
    asm volatile("cp.async.cg.shared.global [%0], [%1], 16;\n" :: "r"(sa), "l"(g));
}
#define CPCOMMIT() asm volatile("cp.async.commit_group;\n" ::: "memory")
#define CPWAIT(n)  asm volatile("cp.async.wait_group %0;\n" :: "n"(n) : "memory")

// ---------------------------------------------------------------------------
// Fused prep: w1 frag-order, w2 frag-order, emb GEMM (block ranges).
// wtrans layout per (mb, 32k-stage s): 2048 u32 = [kk(2)][mt(8)][lane(32)][q(4)]
// ---------------------------------------------------------------------------
__device__ __forceinline__ void wtrans_one(const float* __restrict__ w,
                                           __half* __restrict__ wf,
                                           int i, int K) {
    int m = i / K, k = i % K;
    int S = K >> 5;
    int mb = m >> 7, s = k >> 5;
    int kk = (k >> 4) & 1;
    int mt = (m >> 4) & 7;
    int r = m & 15, c = k & 15;
    int q = (r >> 3) | ((c >> 3) << 1);
    int lane = (r & 7) * 4 + ((c & 7) >> 1);
    size_t b32i = ((((size_t)(mb * S + s) * 2 + kk) * 8 + mt) * 32 + lane) * 4 + q;
    wf[b32i * 2 + (c & 1)] = __float2half_rn(w[i]);
}

#define WBLK ((C_MID * C_IN) / 256)     // 2304 blocks per weight

__global__ void __launch_bounds__(256) prep(const float* __restrict__ w1,
                                            const float* __restrict__ w2,
                                            const float* __restrict__ emb,
                                            const float* __restrict__ we,
                                            const float* __restrict__ be) {
    int bx = blockIdx.x;
    if (bx < WBLK) {
        wtrans_one(w1, g_w1f, bx * 256 + threadIdx.x, C_IN);
    } else if (bx < 2 * WBLK) {
        wtrans_one(w2, g_w2f, (bx - WBLK) * 256 + threadIdx.x, C_MID);
    } else {
        int w = threadIdx.x >> 5, lane = threadIdx.x & 31;
        int j = (bx - 2 * WBLK) * 8 + w;
        const float4* wrow = (const float4*)(we + (size_t)j * EMB_D);
        float4 wv[8];
#pragma unroll
        for (int i = 0; i < 8; i++) wv[i] = wrow[lane + 32 * i];
#pragma unroll
        for (int b = 0; b < BATCH; b++) {
            const float4* er = (const float4*)(emb + (size_t)b * EMB_D);
            float acc = 0.f;
#pragma unroll
            for (int i = 0; i < 8; i++) {
                float4 ev = __ldg(&er[lane + 32 * i]);
                acc += wv[i].x * ev.x + wv[i].y * ev.y + wv[i].z * ev.z + wv[i].w * ev.w;
            }
#pragma unroll
            for (int off = 16; off; off >>= 1) acc += __shfl_xor_sync(0xffffffffu, acc, off);
            if (lane == 0) g_embout[b * (2 * C_MID) + j] = acc + be[j];
        }
    }
}

// ---------------------------------------------------------------------------
// GroupNorm stats + fused xn write (fp16 pair-major).
// ---------------------------------------------------------------------------
__global__ void __launch_bounds__(256) gn_xn(const float* __restrict__ x,
                                             const float* __restrict__ gn_w,
                                             const float* __restrict__ gn_b) {
    int g = blockIdx.x, b = blockIdx.y;
    const float* xp = x + ((size_t)b * C_IN + (size_t)g * CPG) * HW;
    int t = threadIdx.x;
    const int N = CPG * HW;

    float s = 0.f, ss = 0.f;
    for (int i = t * 4; i < N; i += 256 * 4) {
        float4 v = *(const float4*)(xp + i);
        s  += v.x + v.y + v.z + v.w;
        ss += v.x * v.x + v.y * v.y + v.z * v.z + v.w * v.w;
    }
#pragma unroll
    for (int off = 16; off; off >>= 1) {
        s  += __shfl_xor_sync(0xffffffffu, s, off);
        ss += __shfl_xor_sync(0xffffffffu, ss, off);
    }
    __shared__ float rs[8], rss[8];
    if ((t & 31) == 0) { rs[t >> 5] = s; rss[t >> 5] = ss; }
    __syncthreads();
    __shared__ float smu, srst;
    if (t == 0) {
        float S = 0.f, SS = 0.f;
#pragma unroll
        for (int i = 0; i < 8; i++) { S += rs[i]; SS += rss[i]; }
        float mu  = S / (float)N;
        float var = SS / (float)N - mu * mu;
        smu = mu; srst = rsqrtf(var + EPSV);
    }
    __syncthreads();
    const float mu = smu, rst = srst;

    const int n4 = t * 4;
#pragma unroll
    for (int j = 0; j < CPG / 2; j++) {
        int c0 = g * CPG + j * 2;
        float a0 = rst * gn_w[c0],     b0 = gn_b[c0]     - mu * a0;
        float a1 = rst * gn_w[c0 + 1], b1 = gn_b[c0 + 1] - mu * a1;
        float4 x0 = *(const float4*)(x + ((size_t)b * C_IN + c0)     * HW + n4);
        float4 x1 = *(const float4*)(x + ((size_t)b * C_IN + c0 + 1) * HW + n4);
        uint4 o;
        o.x = packh(x0.x * a0 + b0, x1.x * a1 + b1);
        o.y = packh(x0.y * a0 + b0, x1.y * a1 + b1);
        o.z = packh(x0.z * a0 + b0, x1.z * a1 + b1);
        o.w = packh(x0.w * a0 + b0, x1.w * a1 + b1);
        *(uint4*)(g_xn + ((size_t)b * (C_IN / 2) + (c0 >> 1)) * HW + n4) = o;
    }
}

// ---------------------------------------------------------------------------
// fp16 m16n8k16 GEMM, template BK/NSTAGE. Single leading barrier per stage.
// EPI==1 (BK=32,NST=5): silu+FiLM -> g_h fp16. EPI==2 (BK=64,NST=3): +x+b2.
// ---------------------------------------------------------------------------
template <int KTOT, int MTOT, int EPI, int BK, int NST>
__global__ void __launch_bounds__(256, 2) mma_gemm(
    const __half* __restrict__ Wf,
    const u32* __restrict__ Bsrc,
    const float* __restrict__ bias,
    const float* __restrict__ xres,
    float* __restrict__ outp)
{
    constexpr int KK    = BK / 16;
    constexpr int A_U   = BM * BK / 2;
    constexpr int B_U   = (BK / 2) * LDBH;
    constexpr int STG   = A_U + B_U;
    constexpr int S     = KTOT / BK;
    constexpr int MAXW  = NST - 2;

    extern __shared__ float dsm[];
    u32* sm = (u32*)(((uintptr_t)dsm + 1023) & ~(uintptr_t)1023);

    const int t = threadIdx.x;
    const int b = blockIdx.z;
    const int m0 = blockIdx.x * BM;
    const int p0 = blockIdx.y * BN;
    const int wid = t >> 5, lane = t & 31;
    const int gr = lane >> 2, tg = lane & 3;
    const int mt4 = (wid >> 2) * 4;
    const int nw = (wid & 3) * 32;

    const u32* Wb = (const u32*)Wf + (size_t)blockIdx.x * S * A_U;
    const u32* Bb = Bsrc + (size_t)b * (KTOT / 2) * HW + p0;

    float acc[4][4][4];
#pragma unroll
    for (int i = 0; i < 4; i++)
#pragma unroll
        for (int j = 0; j < 4; j++)
#pragma unroll
            for (int q = 0; q < 4; q++) acc[i][j][q] = 0.f;

    auto fill = [&](int st) {
        u32* sA = sm + (st % NST) * STG;
        u32* sB = sA + A_U;
        const u32* gA = Wb + (size_t)st * A_U;
#pragma unroll
        for (int it = 0; it < A_U / 1024; it++)
            cp16(sA + it * 1024 + t * 4, gA + it * 1024 + t * 4);
        // B: (BK/2) pair-rows x 128 u32 -> BK/16 iterations of 256 threads
#pragma unroll
        for (int it = 0; it < BK / 16; it++) {
            int idx = t + it * 256;
            int row = idx >> 5, c4 = (idx & 31) * 4;
            cp16(sB + row * LDBH + c4, Bb + (size_t)(st * (BK / 2) + row) * HW + c4);
        }
        CPCOMMIT();
    };

#pragma unroll
    for (int p = 0; p < NST - 1; p++) fill(p);

    for (int s = 0; s < S; s++) {
        const int rem = S - 1 - s;
        if (MAXW >= 3 && rem >= 3)      { CPWAIT(3); }
        else if (MAXW >= 2 && rem >= 2) { CPWAIT(2); }
        else if (rem >= 1)              { CPWAIT(1); }
        else                            { CPWAIT(0); }
        __syncthreads();
        if (s + NST - 1 < S) fill(s + NST - 1);

        const u32* sA = sm + (s % NST) * STG;
        const u32* sB = sA + A_U;

#pragma unroll
        for (int kk = 0; kk < KK; kk++) {
            u32 af[4][4];
#pragma unroll
            for (int mi = 0; mi < 4; mi++) {
                const uint4 v = *(const uint4*)(sA + ((kk * 8 + mt4 + mi) * 32 + lane) * 4);
                af[mi][0] = v.x; af[mi][1] = v.y; af[mi][2] = v.z; af[mi][3] = v.w;
            }
            u32 bf[4][2];
#pragma unroll
            for (int ni = 0; ni < 4; ni++) {
                int nc = nw + ni * 8 + gr;
                bf[ni][0] = sB[(kk * 8 + tg)     * LDBH + nc];
                bf[ni][1] = sB[(kk * 8 + tg + 4) * LDBH + nc];
            }
#pragma unroll
            for (int mi = 0; mi < 4; mi++)
#pragma unroll
                for (int ni = 0; ni < 4; ni++)
                    mma16(acc[mi][ni], af[mi], bf[ni]);
        }
    }
    __syncthreads();

    // ---------------- epilogue ----------------
    const int mw = mt4 * 16;
    if (EPI == 1) {
        float* tile = (float*)sm;
        const float* sc = g_embout + b * 2 * C_MID;
#pragma unroll
        for (int mi = 0; mi < 4; mi++) {
#pragma unroll
            for (int half = 0; half < 2; half++) {
                int rl = mw + mi * 16 + gr + half * 8;
                int r = m0 + rl;
                float bi    = bias[r];
                float scale = 1.f + sc[r];
                float shift = sc[C_MID + r];
#pragma unroll
                for (int ni = 0; ni < 4; ni++) {
                    float v0 = acc[mi][ni][half * 2]     + bi;
                    float v1 = acc[mi][ni][half * 2 + 1] + bi;
                    v0 = v0 / (1.f + __expf(-v0));
                    v1 = v1 / (1.f + __expf(-v1));
                    float2 o = make_float2(v0 * scale + shift, v1 * scale + shift);
                    *(float2*)(tile + rl * LDT + nw + ni * 8 + tg * 2) = o;
                }
            }
        }
        __syncthreads();
#pragma unroll
        for (int it = 0; it < 8; it++) {
            int idx = t + it * 256;
            int p = idx >> 5, c4 = (idx & 31) * 4;
            const float* r0 = tile + (2 * p)     * LDT + c4;
            const float* r1 = tile + (2 * p + 1) * LDT + c4;
            uint4 o;
            o.x = packh(r0[0], r1[0]);
            o.y = packh(r0[1], r1[1]);
            o.z = packh(r0[2], r1[2]);
            o.w = packh(r0[3], r1[3]);
            *(uint4*)(g_h + ((size_t)b * (C_MID / 2) + (m0 >> 1) + p) * HW + p0 + c4) = o;
        }
    } else {
#pragma unroll
        for (int mi = 0; mi < 4; mi++) {
#pragma unroll
            for (int half = 0; half < 2; half++) {
                int r = m0 + mw + mi * 16 + gr + half * 8;
                float bi = bias[r];
                const float* xrow = xres + ((size_t)b * C_IN + r) * HW + p0 + nw;
                float* orow = outp + ((size_t)b * C_IN + r) * HW + p0 + nw;
#pragma unroll
                for (int ni = 0; ni < 4; ni++) {
                    float2 xv = *(const float2*)(xrow + ni * 8 + tg * 2);
                    float2 o = make_float2(xv.x + acc[mi][ni][half * 2]     + bi,
                                           xv.y + acc[mi][ni][half * 2 + 1] + bi);
                    *(float2*)(orow + ni * 8 + tg * 2) = o;
                }
            }
        }
    }
}

// ---------------------------------------------------------------------------
extern "C" void kernel_launch(void* const* d_in, const int* in_sizes, int n_in,
                              void* d_out, int out_size) {
    const float* x    = (const float*)d_in[0];
    const float* emb  = (const float*)d_in[1];
    const float* gn_w = (const float*)d_in[2];
    const float* gn_b = (const float*)d_in[3];
    const float* w1   = (const float*)d_in[4];
    const float* b1   = (const float*)d_in[5];
    const float* we   = (const float*)d_in[6];
    const float* be   = (const float*)d_in[7];
    const float* w2   = (const float*)d_in[8];
    const float* b2   = (const float*)d_in[9];
    float* out = (float*)d_out;

    u32 *hbuf, *xnbuf;
    __half *w1f, *w2f;
    cudaGetSymbolAddress((void**)&hbuf, g_h);
    cudaGetSymbolAddress((void**)&xnbuf, g_xn);
    cudaGetSymbolAddress((void**)&w1f, g_w1f);
    cudaGetSymbolAddress((void**)&w2f, g_w2f);

    constexpr int SMEMB1 = 5 * (2048 + 16 * LDBH) * 4 + 1024;   // BK=32, NST=5
    constexpr int SMEMB2 = 3 * (4096 + 32 * LDBH) * 4 + 1024;   // BK=64, NST=3

    cudaFuncSetAttribute((const void*)mma_gemm<C_IN, C_MID, 1, 32, 5>,
                         cudaFuncAttributeMaxDynamicSharedMemorySize, SMEMB1);
    cudaFuncSetAttribute((const void*)mma_gemm<C_MID, C_IN, 2, 64, 3>,
                         cudaFuncAttributeMaxDynamicSharedMemorySize, SMEMB2);

    prep<<<2 * WBLK + (2 * C_MID) / 8, 256>>>(w1, w2, emb, we, be);
    gn_xn<<<dim3(GROUPS, BATCH), 256>>>(x, gn_w, gn_b);

    mma_gemm<C_IN, C_MID, 1, 32, 5><<<dim3(C_MID / BM, HW / BN, BATCH), 256, SMEMB1>>>(
        w1f, xnbuf, b1, nullptr, nullptr);
    mma_gemm<C_MID, C_IN, 2, 64, 3><<<dim3(C_IN / BM, HW / BN, BATCH), 256, SMEMB2>>>(
        w2f, hbuf, b2, x, out);
}